// round 17
// baseline (speedup 1.0000x reference)
#include <cuda_runtime.h>
#include <cuda_fp16.h>
#include <cstdint>

// Problem dims (fixed): B=4, N=2048, F_in=128, H=4, D=32
#define Bn 4
#define Nn 2048
#define Fn 128
#define Hn 4
#define Dn 32
#define BH (Bn*Hn)
#define LOG2E 1.4426950408889634f
#define FULLM 0xffffffffu
typedef unsigned long long ull;

__device__ __forceinline__ float ex2(float x) {
    float r; asm("ex2.approx.f32 %0, %1;" : "=f"(r) : "f"(x)); return r;
}
__device__ __forceinline__ ull pack2(float x) {
    ull r; asm("mov.b64 %0, {%1, %1};" : "=l"(r) : "f"(x)); return r;
}
// packed f32x2 score: a0/a1 = max(es1 + e, 0.2*e + es2) for the two packed e's
__device__ __forceinline__ void score2(ull ed2, ull es1x2, ull es2x2, ull c02,
                                       float& a0, float& a1)
{
    ull t1, t2;
    asm("add.rn.f32x2 %0, %1, %2;" : "=l"(t1) : "l"(es1x2), "l"(ed2));
    asm("fma.rn.f32x2 %0, %1, %2, %3;" : "=l"(t2) : "l"(c02), "l"(ed2), "l"(es2x2));
    float t1l, t1h, t2l, t2h;
    asm("mov.b64 {%0,%1}, %2;" : "=f"(t1l), "=f"(t1h) : "l"(t1));
    asm("mov.b64 {%0,%1}, %2;" : "=f"(t2l), "=f"(t2h) : "l"(t2));
    a0 = fmaxf(t1l, t2l);
    a1 = fmaxf(t1h, t2h);
}

// Scratch (device globals; no allocation allowed).
// g_WhT layout: [bh][d][n'] fp16, n' permutes n within each 16-group (B-frag LDS.64).
__device__ __align__(256) __half g_WhT[BH * Dn * Nn];
__device__ __align__(16)  float g_es[BH * Nn];           // e_src (exact fp32)
__device__ __align__(16)  float g_ed[BH * Nn];           // e_dst (exact fp32)
__device__ __align__(256) __half g_W16T[Hn * Dn * Fn];   // W transposed [h][d][f] fp16
__device__ __align__(16)  float g_Was[Hn * Fn];          // W @ a_src  (exact fp32)
__device__ __align__(16)  float g_Wad[Hn * Fn];          // W @ a_dst  (exact fp32)
__device__ __align__(256) unsigned g_mask[Nn * 64];      // adjacency bitmasks (shared by all bh)

// -------------------- Kernel 0: fold a into W; transpose W to fp16 --------------------
// 512 (h,f) rows; grid 16 x 256 threads = 128 warps, 4 rows/warp, lane = d.
__global__ __launch_bounds__(256) void prep_kernel(
    const float* __restrict__ W, const float* __restrict__ a)
{
    const int warp = threadIdx.x >> 5;
    const int lane = threadIdx.x & 31;
    const int wid  = blockIdx.x * 8 + warp;
    const int row0 = wid * 4;
    const int hh   = row0 >> 7;
    const float a_s = __ldg(a + hh * (2 * Dn) + lane);
    const float a_d = __ldg(a + hh * (2 * Dn) + Dn + lane);
    #pragma unroll
    for (int r = 0; r < 4; r++) {
        const int row = row0 + r;
        const int f   = row & 127;
        const float w = __ldg(W + (size_t)row * Dn + lane);
        g_W16T[(hh * Dn + lane) * Fn + f] = __float2half(w);
        float ps = w * a_s, pd = w * a_d;
        #pragma unroll
        for (int off = 16; off; off >>= 1) {
            ps += __shfl_xor_sync(FULLM, ps, off);
            pd += __shfl_xor_sync(FULLM, pd, off);
        }
        if (lane == 0) { g_Was[hh * Fn + f] = ps; g_Wad[hh * Fn + f] = pd; }
    }
}

// -------------------- Kernel A (fused): proj (blocks 0-255) + mask pack (256-511) ----
#define PPAD 136   // h16 row stride (halfs)

__global__ __launch_bounds__(256) void proj_kernel(
    const float* __restrict__ h, const int* __restrict__ adj)
{
    const int tid  = threadIdx.x;
    const int warp = tid >> 5;
    const int lane = tid & 31;

    if (blockIdx.x >= 256) {
        // ---- mask pack: 256 blocks x 8 rows (1 row/warp), once for all 16 bh ----
        const int row = (blockIdx.x - 256) * 8 + warp;
        const int* adjr = adj + (size_t)row * Nn;
        #pragma unroll
        for (int it = 0; it < 16; it++) {
            uint4 av = __ldg((const uint4*)(adjr + it * 128 + lane * 4));
            unsigned m0 = __ballot_sync(FULLM, (int)av.x > 0);
            unsigned m1 = __ballot_sync(FULLM, (int)av.y > 0);
            unsigned m2 = __ballot_sync(FULLM, (int)av.z > 0);
            unsigned m3 = __ballot_sync(FULLM, (int)av.w > 0);
            if (lane == 0)
                *(uint4*)&g_mask[row * 64 + it * 4] = make_uint4(m0, m1, m2, m3);
        }
        return;
    }

    __shared__ __align__(16) __half h16[32 * PPAD];
    const int b  = blockIdx.x >> 6;
    const int n0 = (blockIdx.x & 63) * 32;

    float4 was[4], wad[4];
    #pragma unroll
    for (int hh = 0; hh < 4; hh++) {
        was[hh] = *(const float4*)(g_Was + hh * Fn + lane * 4);
        wad[hh] = *(const float4*)(g_Wad + hh * Fn + lane * 4);
    }

    #pragma unroll
    for (int r = 0; r < 4; r++) {
        const int n = warp * 4 + r;
        const float4 hv = *(const float4*)(h + ((size_t)(b * Nn + n0 + n)) * Fn + lane * 4);
        uint32_t p0, p1;
        asm("cvt.rn.f16x2.f32 %0, %1, %2;" : "=r"(p0) : "f"(hv.y), "f"(hv.x));
        asm("cvt.rn.f16x2.f32 %0, %1, %2;" : "=r"(p1) : "f"(hv.w), "f"(hv.z));
        *(uint2*)&h16[n * PPAD + lane * 4] = make_uint2(p0, p1);
        float p[8];
        #pragma unroll
        for (int hh = 0; hh < 4; hh++) {
            p[hh]     = hv.x * was[hh].x + hv.y * was[hh].y + hv.z * was[hh].z + hv.w * was[hh].w;
            p[4 + hh] = hv.x * wad[hh].x + hv.y * wad[hh].y + hv.z * wad[hh].z + hv.w * wad[hh].w;
        }
        #pragma unroll
        for (int off = 16; off; off >>= 1)
            #pragma unroll
            for (int v = 0; v < 8; v++)
                p[v] += __shfl_xor_sync(FULLM, p[v], off);
        if (lane == 0) {
            #pragma unroll
            for (int hh = 0; hh < 4; hh++) {
                g_es[(b * Hn + hh) * Nn + n0 + n] = p[hh];
                g_ed[(b * Hn + hh) * Nn + n0 + n] = p[4 + hh];
            }
        }
    }
    __syncthreads();

    const int hh = warp & 3;
    const int dh = warp >> 2;
    const int g  = lane >> 2;
    const int qt = lane & 3;
    const __half* Wt = g_W16T + ((size_t)hh * Dn + dh * 16) * Fn;

    float C[4][4];
    #pragma unroll
    for (int nt = 0; nt < 4; nt++)
        #pragma unroll
        for (int k = 0; k < 4; k++) C[nt][k] = 0.f;

    #pragma unroll
    for (int ks = 0; ks < 8; ks++) {
        const int fk = ks * 16 + 2 * qt;
        const uint32_t a0 = *(const uint32_t*)(Wt + (size_t)g * Fn + fk);
        const uint32_t a1 = *(const uint32_t*)(Wt + (size_t)(g + 8) * Fn + fk);
        const uint32_t a2 = *(const uint32_t*)(Wt + (size_t)g * Fn + fk + 8);
        const uint32_t a3 = *(const uint32_t*)(Wt + (size_t)(g + 8) * Fn + fk + 8);
        #pragma unroll
        for (int nt = 0; nt < 4; nt++) {
            const uint32_t b0 = *(const uint32_t*)&h16[(nt * 8 + g) * PPAD + fk];
            const uint32_t b1 = *(const uint32_t*)&h16[(nt * 8 + g) * PPAD + fk + 8];
            asm volatile(
                "mma.sync.aligned.m16n8k16.row.col.f32.f16.f16.f32 "
                "{%0,%1,%2,%3}, {%4,%5,%6,%7}, {%8,%9}, {%0,%1,%2,%3};"
                : "+f"(C[nt][0]), "+f"(C[nt][1]), "+f"(C[nt][2]), "+f"(C[nt][3])
                : "r"(a0), "r"(a1), "r"(a2), "r"(a3), "r"(b0), "r"(b1));
        }
    }

    const int bh = b * Hn + hh;
    uint32_t* w0 = (uint32_t*)g_WhT + (((size_t)bh * Dn + dh * 16 + g) * Nn + n0) / 2;
    uint32_t* w8 = w0 + 8 * (Nn / 2);
    #pragma unroll
    for (int nt = 0; nt < 4; nt++) {
        const int widx = (nt >> 1) * 8 + 2 * qt + (nt & 1);
        uint32_t lo, hi;
        asm("cvt.rn.f16x2.f32 %0, %1, %2;" : "=r"(lo) : "f"(C[nt][1]), "f"(C[nt][0]));
        asm("cvt.rn.f16x2.f32 %0, %1, %2;" : "=r"(hi) : "f"(C[nt][3]), "f"(C[nt][2]));
        w0[widx] = lo;
        w8[widx] = hi;
    }
}

// -------------------- Kernel B: masked softmax + P@Wh via fp16 MMA --------------------
#define TJm 128
#define NMT (Nn / TJm)
#define WSTh 144
#define CST 34

__global__ __launch_bounds__(256, 3) void attn_kernel(float* __restrict__ out)
{
    __shared__ __align__(16) float    ed_sm[Nn];             // 8 KB
    __shared__ __align__(16) unsigned mask_sm[64 * 64];      // 16 KB (cp.async; C scratch later)
    __shared__ __align__(16) __half   wh_sm[2][32 * WSTh];   // 18 KB double buffer
    __shared__ float es1_sm[64], es2_sm[64];

    const int bh = blockIdx.x;
    const int b  = bh >> 2;
    const int hd = bh & 3;
    const int rbase = blockIdx.y * 64;
    const int tid  = threadIdx.x;
    const int warp = tid >> 5;
    const int lane = tid & 31;
    const int g  = lane >> 2;
    const int qt = lane & 3;
    const int par = warp >> 2;
    const int lrA = (warp & 3) * 16 + g;
    const int lrB = lrA + 8;
    const unsigned lanebit = 1u << lane;

    const __half* whg = g_WhT + (size_t)bh * Dn * Nn;

    // ---- group 0: cp.async adjacency masks (16 KB) ----
    #pragma unroll
    for (int tt = 0; tt < 4; tt++) {
        const int idx = tid + tt * 256;
        uint32_t dp = (uint32_t)__cvta_generic_to_shared(&mask_sm[idx * 4]);
        asm volatile("cp.async.ca.shared.global [%0], [%1], 16;"
                     :: "r"(dp), "l"(&g_mask[(size_t)rbase * 64 + idx * 4]));
    }
    asm volatile("cp.async.commit_group;" ::: "memory");

    // ---- stage e_dst (scaled to log2 units) ----
    {
        const float4* src = (const float4*)(g_ed + bh * Nn);
        float4* dst = (float4*)ed_sm;
        #pragma unroll
        for (int r = 0; r < 2; r++) {
            float4 v = src[tid + r * 256];
            v.x *= LOG2E; v.y *= LOG2E; v.z *= LOG2E; v.w *= LOG2E;
            dst[tid + r * 256] = v;
        }
    }

    // ---- groups 1,2: prefetch WhT metas 0,1 ----
    #pragma unroll
    for (int c = 0; c < 2; c++) {
        #pragma unroll
        for (int tt = 0; tt < 2; tt++) {
            const int idx = tid + tt * 256;
            const int row = idx >> 4, seg = idx & 15;
            uint32_t dp = (uint32_t)__cvta_generic_to_shared(&wh_sm[c][row * WSTh + seg * 8]);
            asm volatile("cp.async.ca.shared.global [%0], [%1], 16;"
                         :: "r"(dp), "l"(whg + (size_t)row * Nn + c * TJm + seg * 8));
        }
        asm volatile("cp.async.commit_group;" ::: "memory");
    }

    asm volatile("cp.async.wait_group 2;" ::: "memory");   // masks landed
    __syncthreads();   // ed_sm + mask_sm ready

    // ---- Pass 1: exact masked row max from precomputed bitmasks ----
    for (int k = 0; k < 8; k++) {
        const int lr = warp * 8 + k;
        float m = -1e30f;
        #pragma unroll
        for (int it = 0; it < 16; it++) {
            const uint4 mw = *(const uint4*)&mask_sm[lr * 64 + it * 4];   // broadcast
            const float4 ev = *(const float4*)&ed_sm[it * 128 + lane * 4];
            if (mw.x & lanebit) m = fmaxf(m, ev.x);
            if (mw.y & lanebit) m = fmaxf(m, ev.y);
            if (mw.z & lanebit) m = fmaxf(m, ev.z);
            if (mw.w & lanebit) m = fmaxf(m, ev.w);
        }
        #pragma unroll
        for (int off = 16; off; off >>= 1) m = fmaxf(m, __shfl_xor_sync(FULLM, m, off));
        if (lane == 0) {
            const float es = __ldg(g_es + bh * Nn + rbase + lr) * LOG2E;
            float e1, e2;
            if (m < -9e29f) { e1 = -1e9f; e2 = -1e9f; }
            else {
                float s = es + m;
                float M = fmaxf(s, 0.2f * s);
                e1 = es - M;
                e2 = 0.2f * es - M;
            }
            es1_sm[lr] = e1; es2_sm[lr] = e2;
        }
    }
    __syncthreads();

    const ull esA1x2 = pack2(es1_sm[lrA]), esA2x2 = pack2(es2_sm[lrA]);
    const ull esB1x2 = pack2(es1_sm[lrB]), esB2x2 = pack2(es2_sm[lrB]);
    const ull C02 = pack2(0.2f);

    // ---- Pass 2: P (fp16 A-fragment) @ WhT via mma.m16n8k16; tile 4 yields l ----
    float C[5][4];
    #pragma unroll
    for (int nt = 0; nt < 5; nt++)
        #pragma unroll
        for (int k = 0; k < 4; k++) C[nt][k] = 0.f;

    const int c0 = 2 * (qt & 1);
    const int psh = par * 16 + (qt >> 1);
    const uint32_t blx = (g == 0) ? 0x3C003C00u : 0u;   // constant ones-column B-fragment

    for (int t = 0; t < NMT; t++) {
        asm volatile("cp.async.wait_group 1;" ::: "memory");
        __syncthreads();

        const uint2 mwA = *(const uint2*)&mask_sm[lrA * 64 + (t << 2) + c0];
        const uint2 mwB = *(const uint2*)&mask_sm[lrB * 64 + (t << 2) + c0];
        const unsigned wA0 = mwA.x >> psh;
        const unsigned wA1 = mwA.y >> psh;
        const unsigned wB0 = mwB.x >> psh;
        const unsigned wB1 = mwB.y >> psh;
        const int jb = t * TJm + par * 64;
        const __half* wbuf = wh_sm[t & 1] + par * 64;

        #pragma unroll
        for (int ks = 0; ks < 4; ks++) {
            const int j0 = jb + ks * 16 + 2 * qt;
            const ull ed2lo = *(const ull*)(ed_sm + j0);
            const ull ed2hi = *(const ull*)(ed_sm + j0 + 8);
            float aA0, aA1, aA8, aA9, aB0, aB1, aB8, aB9;
            score2(ed2lo, esA1x2, esA2x2, C02, aA0, aA1);
            score2(ed2hi, esA1x2, esA2x2, C02, aA8, aA9);
            score2(ed2lo, esB1x2, esB2x2, C02, aB0, aB1);
            score2(ed2hi, esB1x2, esB2x2, C02, aB8, aB9);
            float pA0 = 0.f, pA1 = 0.f, pA8 = 0.f, pA9 = 0.f;
            float pB0 = 0.f, pB1 = 0.f, pB8 = 0.f, pB9 = 0.f;
            if (wA0 & (1u << (4 * ks)))     pA0 = ex2(aA0);
            if (wA1 & (1u << (4 * ks)))     pA1 = ex2(aA1);
            if (wA0 & (1u << (4 * ks + 2))) pA8 = ex2(aA8);
            if (wA1 & (1u << (4 * ks + 2))) pA9 = ex2(aA9);
            if (wB0 & (1u << (4 * ks)))     pB0 = ex2(aB0);
            if (wB1 & (1u << (4 * ks)))     pB1 = ex2(aB1);
            if (wB0 & (1u << (4 * ks + 2))) pB8 = ex2(aB8);
            if (wB1 & (1u << (4 * ks + 2))) pB9 = ex2(aB9);
            uint32_t a0, a1, a2, a3;
            asm("cvt.rn.f16x2.f32 %0, %1, %2;" : "=r"(a0) : "f"(pA1), "f"(pA0));
            asm("cvt.rn.f16x2.f32 %0, %1, %2;" : "=r"(a1) : "f"(pB1), "f"(pB0));
            asm("cvt.rn.f16x2.f32 %0, %1, %2;" : "=r"(a2) : "f"(pA9), "f"(pA8));
            asm("cvt.rn.f16x2.f32 %0, %1, %2;" : "=r"(a3) : "f"(pB9), "f"(pB8));
            const __half* bpt = wbuf + ks * 16 + 4 * qt;
            #pragma unroll
            for (int nt = 0; nt < 4; nt++) {
                const uint2 bb = *(const uint2*)(bpt + (nt * 8 + g) * WSTh);
                asm volatile(
                    "mma.sync.aligned.m16n8k16.row.col.f32.f16.f16.f32 "
                    "{%0,%1,%2,%3}, {%4,%5,%6,%7}, {%8,%9}, {%0,%1,%2,%3};"
                    : "+f"(C[nt][0]), "+f"(C[nt][1]), "+f"(C[nt][2]), "+f"(C[nt][3])
                    : "r"(a0), "r"(a1), "r"(a2), "r"(a3), "r"(bb.x), "r"(bb.y));
            }
            asm volatile(
                "mma.sync.aligned.m16n8k16.row.col.f32.f16.f16.f32 "
                "{%0,%1,%2,%3}, {%4,%5,%6,%7}, {%8,%9}, {%0,%1,%2,%3};"
                : "+f"(C[4][0]), "+f"(C[4][1]), "+f"(C[4][2]), "+f"(C[4][3])
                : "r"(a0), "r"(a1), "r"(a2), "r"(a3), "r"(blx), "r"(blx));
        }

        __syncthreads();
        const int nc = t + 2;
        if (nc < NMT) {
            #pragma unroll
            for (int tt = 0; tt < 2; tt++) {
                const int idx = tid + tt * 256;
                const int row = idx >> 4, seg = idx & 15;
                uint32_t dp = (uint32_t)__cvta_generic_to_shared(&wh_sm[nc & 1][row * WSTh + seg * 8]);
                asm volatile("cp.async.ca.shared.global [%0], [%1], 16;"
                             :: "r"(dp), "l"(whg + (size_t)row * Nn + nc * TJm + seg * 8));
            }
        }
        asm volatile("cp.async.commit_group;" ::: "memory");
    }

    const float lA = __shfl_sync(FULLM, C[4][0], lane & ~3);
    const float lB = __shfl_sync(FULLM, C[4][2], lane & ~3);

    // ---- Combine the two j-halves (warps w and w+4 hold the same rows) ----
    float* Csc = (float*)mask_sm;
    float* lsc = Csc + 64 * CST;
    if (par == 1) {
        #pragma unroll
        for (int nt = 0; nt < 4; nt++) {
            *(float2*)&Csc[lrA * CST + nt * 8 + 2 * qt] = make_float2(C[nt][0], C[nt][1]);
            *(float2*)&Csc[lrB * CST + nt * 8 + 2 * qt] = make_float2(C[nt][2], C[nt][3]);
        }
        if (qt == 0) { lsc[lrA] = lA; lsc[lrB] = lB; }
    }
    __syncthreads();
    if (par == 0) {
        #pragma unroll
        for (int nt = 0; nt < 4; nt++) {
            float2 cA = *(const float2*)&Csc[lrA * CST + nt * 8 + 2 * qt];
            float2 cB = *(const float2*)&Csc[lrB * CST + nt * 8 + 2 * qt];
            C[nt][0] += cA.x; C[nt][1] += cA.y;
            C[nt][2] += cB.x; C[nt][3] += cB.y;
        }
        const float tlA = lA + lsc[lrA];
        const float tlB = lB + lsc[lrB];
        const float rlA = (tlA > 0.f) ? (1.f / tlA) : 0.f;
        const float rlB = (tlB > 0.f) ? (1.f / tlB) : 0.f;
        const int iA = rbase + lrA;
        const int iB = rbase + lrB;
        float* outA = out + (size_t)(b * Nn + iA) * (Hn * Dn) + hd * Dn + 2 * qt;
        float* outB = out + (size_t)(b * Nn + iB) * (Hn * Dn) + hd * Dn + 2 * qt;
        #pragma unroll
        for (int nt = 0; nt < 4; nt++) {
            *(float2*)(outA + nt * 8) = make_float2(C[nt][0] * rlA, C[nt][1] * rlA);
            *(float2*)(outB + nt * 8) = make_float2(C[nt][2] * rlB, C[nt][3] * rlB);
        }
    }
}

extern "C" void kernel_launch(void* const* d_in, const int* in_sizes, int n_in,
                              void* d_out, int out_size)
{
    // Bind inputs by element count (robust to metadata ordering)
    const float* h = nullptr; const int* adj = nullptr;
    const float* W = nullptr; const float* a = nullptr;
    for (int i = 0; i < n_in; i++) {
        switch (in_sizes[i]) {
            case 1048576: h   = (const float*)d_in[i]; break;
            case 4194304: adj = (const int*)  d_in[i]; break;
            case 16384:   W   = (const float*)d_in[i]; break;
            case 256:     a   = (const float*)d_in[i]; break;
        }
    }
    float* out = (float*)d_out;

    prep_kernel<<<16, 256>>>(W, a);
    proj_kernel<<<512, 256>>>(h, adj);
    attn_kernel<<<dim3(BH, Nn / 64), 256>>>(out);
}